// round 6
// baseline (speedup 1.0000x reference)
#include <cuda_runtime.h>
#include <math.h>

// Problem constants
#define Bb   4
#define Tt   4096
#define Ww   1024
#define Hh   8
#define BW   128        // channels per head
#define TC   128        // tokens per tile / scan chunk
#define CC   (Tt / TC)  // chunks per sequence = 32
#define NW   256        // output cols per head tile (w_in | w_a)
#define XP   132        // padded m-stride for x tile [k][m] (MULTIPLE OF 4: float4 loads)

// Look-back mailbox: per (chain, tile, channel) packed (valid<<32 | carry bits).
// chain = h*Bb + b (32 chains), tile = 0..31, channel = 0..127.
// Zero-initialized at load; consumers reset their predecessor's slots so every
// graph replay starts from all-zero flags.
__device__ unsigned long long g_cf[32 * CC * BW];

// smem float offsets
// [0, 32768)            ws [128][256]  (reused after GEMM: sA [0,16384) | sX [16384,32768))
// [32768, +16896)       xt [k][m] stride XP=132
// then sp 128 | bia 256 | rst 128 | sF 512 | sP 512 | sSeed 512
#define SM_XT   32768
#define SM_SP   (SM_XT + 128 * XP)
#define SM_BIA  (SM_SP + 128)
#define SM_RST  (SM_BIA + 256)
#define SM_SF   (SM_RST + 128)
#define SM_SPP  (SM_SF + 512)
#define SM_SEED (SM_SPP + 512)
#define SM_TOT  (SM_SEED + 512)
#define SMEM_BYTES (SM_TOT * 4)         // 206,848 B

// ---------------------------------------------------------------------------
// Single fused kernel: block-diag GEMM (both gates) + fast elementwise
// + chunk scan + decoupled look-back carry + apply + store out.
// grid (32 tiles, 4 batch, 8 heads), 512 threads, 1 CTA/SM.
// tile = blockIdx.x (fastest) so a tile's predecessor is always dispatched
// no later than the tile itself -> spin-wait is deadlock-free.
// ---------------------------------------------------------------------------
__global__ void __launch_bounds__(512, 1)
k_fused(const float* __restrict__ x, const int* __restrict__ segp,
        const float* __restrict__ a_param,
        const float* __restrict__ w_in, const float* __restrict__ b_in,
        const float* __restrict__ w_a,  const float* __restrict__ b_a,
        float* __restrict__ out)
{
    extern __shared__ float sm[];
    float* ws   = sm;
    float* xt   = sm + SM_XT;
    float* sp   = sm + SM_SP;
    float* bia  = sm + SM_BIA;
    float* rst  = sm + SM_RST;
    float* sF   = sm + SM_SF;
    float* sP   = sm + SM_SPP;
    float* sSd  = sm + SM_SEED;

    const int tid  = threadIdx.x;
    const int tile = blockIdx.x;
    const int b    = blockIdx.y;
    const int hd   = blockIdx.z;
    const int t0   = tile * TC;

    // ---- weights: ws[i][0..127]=w_in[hd][i][:], ws[i][128..255]=w_a[hd][i][:]
    {
        const float4* win4 = reinterpret_cast<const float4*>(w_in + hd * BW * BW);
        const float4* wa4  = reinterpret_cast<const float4*>(w_a  + hd * BW * BW);
        float4* ws4 = reinterpret_cast<float4*>(ws);
        #pragma unroll
        for (int it = 0; it < 8; ++it) {
            int f4 = tid + it * 512;           // 0..4095
            int i  = f4 >> 5;
            int jq = f4 & 31;
            ws4[i * 64 + jq]      = win4[f4];
            ws4[i * 64 + 32 + jq] = wa4[f4];
        }
    }

    // ---- x tile transposed into [k][m] (global coalesced)
    {
        const int warp = tid >> 5, lane = tid & 31;
        #pragma unroll
        for (int r = 0; r < 8; ++r) {
            int m = warp * 8 + r;
            const float* xr = x + (size_t)(b * Tt + t0 + m) * Ww + hd * BW;
            #pragma unroll
            for (int j = 0; j < 4; ++j) {
                int k = lane + j * 32;
                xt[k * XP + m] = xr[k];
            }
        }
    }

    // ---- per-channel / per-token small data
    if (tid < 128) {
        sp[tid]  = log1pf(expf(a_param[hd * BW + tid]));   // precise softplus (once)
        bia[tid] = b_in[hd * BW + tid];
        rst[tid] = (segp[b * Tt + t0 + tid] == 0) ? 0.f : 1.f;
    } else if (tid < 256) {
        bia[tid] = b_a[hd * BW + (tid - 128)];
    }
    __syncthreads();

    // ---- GEMM: z[128 tok][256 col]; thread tile 8 tok x (4 gx + 4 ga cols)
    const int tx = tid & 31;
    const int ty = tid >> 5;
    const int m0 = ty * 8;
    const int c0 = tx * 4;

    float acc[8][8];
    #pragma unroll
    for (int i = 0; i < 8; ++i)
        #pragma unroll
        for (int j = 0; j < 8; ++j) acc[i][j] = 0.f;

    #pragma unroll 4
    for (int k = 0; k < 128; ++k) {
        float4 xa = *reinterpret_cast<const float4*>(&xt[k * XP + m0]);      // broadcast
        float4 xb = *reinterpret_cast<const float4*>(&xt[k * XP + m0 + 4]);  // broadcast
        float4 w0 = *reinterpret_cast<const float4*>(&ws[k * NW + c0]);        // dense
        float4 w1 = *reinterpret_cast<const float4*>(&ws[k * NW + 128 + c0]);  // dense
        float xv[8] = {xa.x, xa.y, xa.z, xa.w, xb.x, xb.y, xb.z, xb.w};
        float wv[8] = {w0.x, w0.y, w0.z, w0.w, w1.x, w1.y, w1.z, w1.w};
        #pragma unroll
        for (int i = 0; i < 8; ++i)
            #pragma unroll
            for (int j = 0; j < 8; ++j)
                acc[i][j] = fmaf(xv[i], wv[j], acc[i][j]);
    }

    // pull per-column constants into regs before ws region is repurposed
    float bz0[4], bz1[4], sp4[4];
    #pragma unroll
    for (int j = 0; j < 4; ++j) {
        bz0[j] = bia[c0 + j];
        bz1[j] = bia[128 + c0 + j];
        sp4[j] = sp[c0 + j];
    }
    __syncthreads();

    // ---- fused epilogue (fast math): a, xn into smem
    float* sA = sm;            // a  [m][c]
    float* sX = sm + 16384;    // xn [m][c]
    {
        const float* xrow = x + (size_t)(b * Tt + t0) * Ww + hd * BW + c0;
        #pragma unroll
        for (int mi = 0; mi < 8; ++mi) {
            const int m = m0 + mi;
            float4 xg = *reinterpret_cast<const float4*>(xrow + (size_t)m * Ww);
            float keep = rst[m];
            float av[4], xnv[4];
            #pragma unroll
            for (int j = 0; j < 4; ++j) {
                float zx  = acc[mi][j]     + bz0[j];
                float za  = acc[mi][j + 4] + bz1[j];
                float gxv = __fdividef(1.f, 1.f + __expf(-zx));
                float gav = __fdividef(1.f, 1.f + __expf(-za));
                float la  = -8.f * gav * sp4[j];
                float a   = __expf(la) * keep;
                // -expm1(2*la), cancellation-free:
                float u   = 2.f * la;                       // u <= 0
                float t   = __expf(u);
                float pol = -u * fmaf(u, fmaf(u, 0.16666667f, 0.5f), 1.f);
                float arg = (u > -0.01f) ? pol : (1.f - t);
                float mlt = sqrtf(fmaxf(arg, 0.f));
                av[j]  = a;
                xnv[j] = (&xg.x)[j] * gxv * mlt;
            }
            *reinterpret_cast<float4*>(&sA[m * 128 + c0]) =
                make_float4(av[0], av[1], av[2], av[3]);
            *reinterpret_cast<float4*>(&sX[m * 128 + c0]) =
                make_float4(xnv[0], xnv[1], xnv[2], xnv[3]);
        }
    }
    __syncthreads();

    // ---- per-chunk local scan, 4 token segments of 32
    {
        const int c = tid & 127;
        const int s = tid >> 7;
        float hs = 0.f, pr = 1.f;
        const int mb = s * 32;
        #pragma unroll 8
        for (int mi = 0; mi < 32; ++mi) {
            int m = mb + mi;
            float a  = sA[m * 128 + c];
            float xn = sX[m * 128 + c];
            hs = fmaf(a, hs, xn);
            pr *= a;
        }
        sF[s * 128 + c] = hs;
        sP[s * 128 + c] = pr;
    }
    __syncthreads();

    // ---- decoupled look-back: per-channel independent carry chains
    if (tid < 128) {
        const int c = tid;
        // combine 4 segments -> chunk (Pc, Fc)
        float Fc = sF[c], Pc = sP[c];
        #pragma unroll
        for (int s = 1; s < 4; ++s) {
            float ps = sP[s * 128 + c];
            Fc = fmaf(ps, Fc, sF[s * 128 + c]);
            Pc *= ps;
        }
        const int cid = hd * Bb + b;
        float cin = 0.f;
        if (tile > 0) {
            unsigned long long* pp = g_cf + (((size_t)cid * CC + (tile - 1)) << 7) + c;
            unsigned long long v;
            do {
                asm volatile("ld.acquire.gpu.global.b64 %0, [%1];"
                             : "=l"(v) : "l"(pp) : "memory");
            } while ((v >> 32) == 0ull);
            cin = __uint_as_float((unsigned)(v & 0xffffffffull));
            *(volatile unsigned long long*)pp = 0ull;   // reset for next replay
        }
        float cout = fmaf(Pc, cin, Fc);
        unsigned long long* myp = g_cf + (((size_t)cid * CC + tile) << 7) + c;
        unsigned long long pk = (1ull << 32) |
                                (unsigned long long)__float_as_uint(cout);
        asm volatile("st.release.gpu.global.b64 [%0], %1;"
                     :: "l"(myp), "l"(pk) : "memory");
        // segment seeds: seed(s) = scan state entering segment s
        float hseed = cin;
        #pragma unroll
        for (int s = 0; s < 4; ++s) {
            sSd[s * 128 + c] = hseed;
            hseed = fmaf(sP[s * 128 + c], hseed, sF[s * 128 + c]);
        }
    }
    __syncthreads();

    // ---- apply: seeded scan per segment, write out (coalesced)
    {
        const int c = tid & 127;
        const int s = tid >> 7;
        float hv = sSd[s * 128 + c];
        const int mb = s * 32;
        float* op = out + (size_t)(b * Tt + t0 + mb) * Ww + hd * BW + c;
        #pragma unroll 4
        for (int mi = 0; mi < 32; ++mi) {
            int m = mb + mi;
            hv = fmaf(sA[m * 128 + c], hv, sX[m * 128 + c]);
            op[(size_t)mi * Ww] = hv;
        }
    }
}

// ---------------------------------------------------------------------------
extern "C" void kernel_launch(void* const* d_in, const int* in_sizes, int n_in,
                              void* d_out, int out_size)
{
    (void)in_sizes; (void)n_in; (void)out_size;
    const float* x       = (const float*)d_in[0];
    const int*   segp    = (const int*)  d_in[1];
    const float* a_param = (const float*)d_in[2];
    const float* w_in    = (const float*)d_in[3];
    const float* b_in    = (const float*)d_in[4];
    const float* w_a     = (const float*)d_in[5];
    const float* b_a     = (const float*)d_in[6];
    float* out = (float*)d_out;

    cudaFuncSetAttribute(k_fused, cudaFuncAttributeMaxDynamicSharedMemorySize,
                         SMEM_BYTES);

    k_fused<<<dim3(CC, Bb, Hh), 512, SMEM_BYTES>>>(
        x, segp, a_param, w_in, b_in, w_a, b_a, out);
}

// round 7
// speedup vs baseline: 1.2426x; 1.2426x over previous
#include <cuda_runtime.h>
#include <math.h>

// Problem constants
#define Bb   4
#define Tt   4096
#define Ww   1024
#define Hh   8
#define BW   128        // channels per head
#define TC   128        // tokens per tile / scan chunk
#define CC   (Tt / TC)  // chunks per sequence = 32
#define NW   256        // output cols per head tile (w_in | w_a)
#define XP   132        // padded m-stride for x tile [k][m] (multiple of 4: float4)

// Decoupled look-back state: 32 chains x 32 tiles x 128 channels.
// agg (P,F) write-once; inc write-once; flag: 0=empty, 1=agg ready, 2=inc ready.
#define NSLOT (32 * CC * BW)
__device__ float        g_aggP[NSLOT];
__device__ float        g_aggF[NSLOT];
__device__ float        g_inc [NSLOT];
__device__ unsigned int g_flag[NSLOT];   // zero-initialized; cleanup re-zeroes

// smem float offsets
// [0, 32768)      ws [128][256]  (reused after GEMM: sA [0,16384) | sX [16384,32768))
// [32768,+16896)  xt [k][m] stride XP=132
// then sp 128 | bia 256 | rst 128 | sF 512 | sP 512 | sSeed 512
#define SM_XT   32768
#define SM_SP   (SM_XT + 128 * XP)
#define SM_BIA  (SM_SP + 128)
#define SM_RST  (SM_BIA + 256)
#define SM_SF   (SM_RST + 128)
#define SM_SPP  (SM_SF + 512)
#define SM_SEED (SM_SPP + 512)
#define SM_TOT  (SM_SEED + 512)
#define SMEM_BYTES (SM_TOT * 4)         // 206,848 B

// ---------------------------------------------------------------------------
// Single fused kernel: block-diag GEMM (both gates) + fast elementwise
// + chunk scan + DECOUPLED look-back (aggregate walk, no serial ripple)
// + apply + store out.  grid (32 tiles, 4 batch, 8 heads), 512 thr, 1 CTA/SM.
// ---------------------------------------------------------------------------
__global__ void __launch_bounds__(512, 1)
k_fused(const float* __restrict__ x, const int* __restrict__ segp,
        const float* __restrict__ a_param,
        const float* __restrict__ w_in, const float* __restrict__ b_in,
        const float* __restrict__ w_a,  const float* __restrict__ b_a,
        float* __restrict__ out)
{
    extern __shared__ float sm[];
    float* ws   = sm;
    float* xt   = sm + SM_XT;
    float* sp   = sm + SM_SP;
    float* bia  = sm + SM_BIA;
    float* rst  = sm + SM_RST;
    float* sF   = sm + SM_SF;
    float* sP   = sm + SM_SPP;
    float* sSd  = sm + SM_SEED;

    const int tid  = threadIdx.x;
    const int tile = blockIdx.x;       // fastest grid dim -> predecessors never later
    const int b    = blockIdx.y;
    const int hd   = blockIdx.z;
    const int t0   = tile * TC;

    // ---- weights: ws[i][0..127]=w_in[hd][i][:], ws[i][128..255]=w_a[hd][i][:]
    {
        const float4* win4 = reinterpret_cast<const float4*>(w_in + hd * BW * BW);
        const float4* wa4  = reinterpret_cast<const float4*>(w_a  + hd * BW * BW);
        float4* ws4 = reinterpret_cast<float4*>(ws);
        #pragma unroll
        for (int it = 0; it < 8; ++it) {
            int f4 = tid + it * 512;           // 0..4095
            int i  = f4 >> 5;
            int jq = f4 & 31;
            ws4[i * 64 + jq]      = win4[f4];
            ws4[i * 64 + 32 + jq] = wa4[f4];
        }
    }

    // ---- x tile transposed into [k][m] (global coalesced)
    {
        const int warp = tid >> 5, lane = tid & 31;
        #pragma unroll
        for (int r = 0; r < 8; ++r) {
            int m = warp * 8 + r;
            const float* xr = x + (size_t)(b * Tt + t0 + m) * Ww + hd * BW;
            #pragma unroll
            for (int j = 0; j < 4; ++j) {
                int k = lane + j * 32;
                xt[k * XP + m] = xr[k];
            }
        }
    }

    // ---- per-channel / per-token small data
    if (tid < 128) {
        sp[tid]  = log1pf(expf(a_param[hd * BW + tid]));   // precise softplus (once)
        bia[tid] = b_in[hd * BW + tid];
        rst[tid] = (segp[b * Tt + t0 + tid] == 0) ? 0.f : 1.f;
    } else if (tid < 256) {
        bia[tid] = b_a[hd * BW + (tid - 128)];
    }
    __syncthreads();

    // ---- GEMM: z[128 tok][256 col]; thread tile 8 tok x (4 gx + 4 ga cols)
    const int tx = tid & 31;
    const int ty = tid >> 5;
    const int m0 = ty * 8;
    const int c0 = tx * 4;

    float acc[8][8];
    #pragma unroll
    for (int i = 0; i < 8; ++i)
        #pragma unroll
        for (int j = 0; j < 8; ++j) acc[i][j] = 0.f;

    #pragma unroll 4
    for (int k = 0; k < 128; ++k) {
        float4 xa = *reinterpret_cast<const float4*>(&xt[k * XP + m0]);      // broadcast
        float4 xb = *reinterpret_cast<const float4*>(&xt[k * XP + m0 + 4]);  // broadcast
        float4 w0 = *reinterpret_cast<const float4*>(&ws[k * NW + c0]);        // dense
        float4 w1 = *reinterpret_cast<const float4*>(&ws[k * NW + 128 + c0]);  // dense
        float xv[8] = {xa.x, xa.y, xa.z, xa.w, xb.x, xb.y, xb.z, xb.w};
        float wv[8] = {w0.x, w0.y, w0.z, w0.w, w1.x, w1.y, w1.z, w1.w};
        #pragma unroll
        for (int i = 0; i < 8; ++i)
            #pragma unroll
            for (int j = 0; j < 8; ++j)
                acc[i][j] = fmaf(xv[i], wv[j], acc[i][j]);
    }

    // pull per-column constants into regs before ws region is repurposed
    float bz0[4], bz1[4], sp4[4];
    #pragma unroll
    for (int j = 0; j < 4; ++j) {
        bz0[j] = bia[c0 + j];
        bz1[j] = bia[128 + c0 + j];
        sp4[j] = sp[c0 + j];
    }
    __syncthreads();

    // ---- fused epilogue (fast math): a, xn into smem
    float* sA = sm;            // a  [m][c]
    float* sX = sm + 16384;    // xn [m][c]
    {
        const float* xrow = x + (size_t)(b * Tt + t0) * Ww + hd * BW + c0;
        #pragma unroll
        for (int mi = 0; mi < 8; ++mi) {
            const int m = m0 + mi;
            float4 xg = *reinterpret_cast<const float4*>(xrow + (size_t)m * Ww);
            float keep = rst[m];
            float av[4], xnv[4];
            #pragma unroll
            for (int j = 0; j < 4; ++j) {
                float zx  = acc[mi][j]     + bz0[j];
                float za  = acc[mi][j + 4] + bz1[j];
                float gxv = __fdividef(1.f, 1.f + __expf(-zx));
                float gav = __fdividef(1.f, 1.f + __expf(-za));
                float la  = -8.f * gav * sp4[j];
                float a   = __expf(la) * keep;
                // -expm1(2*la), cancellation-free:
                float u   = 2.f * la;                       // u <= 0
                float t   = __expf(u);
                float pol = -u * fmaf(u, fmaf(u, 0.16666667f, 0.5f), 1.f);
                float arg = (u > -0.01f) ? pol : (1.f - t);
                float mlt = sqrtf(fmaxf(arg, 0.f));
                av[j]  = a;
                xnv[j] = (&xg.x)[j] * gxv * mlt;
            }
            *reinterpret_cast<float4*>(&sA[m * 128 + c0]) =
                make_float4(av[0], av[1], av[2], av[3]);
            *reinterpret_cast<float4*>(&sX[m * 128 + c0]) =
                make_float4(xnv[0], xnv[1], xnv[2], xnv[3]);
        }
    }
    __syncthreads();

    // ---- per-chunk local scan, 4 token segments of 32
    {
        const int c = tid & 127;
        const int s = tid >> 7;
        float hs = 0.f, pr = 1.f;
        const int mb = s * 32;
        #pragma unroll 8
        for (int mi = 0; mi < 32; ++mi) {
            int m = mb + mi;
            float a  = sA[m * 128 + c];
            float xn = sX[m * 128 + c];
            hs = fmaf(a, hs, xn);
            pr *= a;
        }
        sF[s * 128 + c] = hs;
        sP[s * 128 + c] = pr;
    }
    __syncthreads();

    // ---- decoupled look-back: publish aggregate, walk predecessors' aggregates
    if (tid < 128) {
        const int c = tid;
        // combine 4 segments -> chunk (Pc, Fc)
        float Fc = sF[c], Pc = sP[c];
        #pragma unroll
        for (int s = 1; s < 4; ++s) {
            float ps = sP[s * 128 + c];
            Fc = fmaf(ps, Fc, sF[s * 128 + c]);
            Pc *= ps;
        }
        const int cid  = hd * Bb + b;
        const int cbase = (cid * CC) << 7;          // chain base slot
        const int me    = cbase + (tile << 7) + c;

        // publish aggregate (write-once payload, then release flag=1)
        g_aggP[me] = Pc;
        g_aggF[me] = Fc;
        asm volatile("st.release.gpu.global.b32 [%0], %1;"
                     :: "l"(g_flag + me), "r"(1u) : "memory");

        // walk backwards over predecessors
        float cin = 0.f, pacc = 1.f;
        for (int k = tile - 1; k >= 0; --k) {
            const int idx = cbase + (k << 7) + c;
            unsigned fl;
            do {
                asm volatile("ld.acquire.gpu.global.b32 %0, [%1];"
                             : "=r"(fl) : "l"(g_flag + idx) : "memory");
            } while (fl == 0u);
            if (fl == 2u) {                          // predecessor inclusive known
                cin = fmaf(pacc, g_inc[idx], cin);
                break;
            }
            cin = fmaf(pacc, g_aggF[idx], cin);      // fold its aggregate
            pacc *= g_aggP[idx];
        }

        // publish inclusive (write-once), release flag=2
        float Hme = fmaf(Pc, cin, Fc);
        g_inc[me] = Hme;
        asm volatile("st.release.gpu.global.b32 [%0], %1;"
                     :: "l"(g_flag + me), "r"(2u) : "memory");

        // segment seeds: seed(s) = scan state entering segment s
        float hseed = cin;
        #pragma unroll
        for (int s = 0; s < 4; ++s) {
            sSd[s * 128 + c] = hseed;
            hseed = fmaf(sP[s * 128 + c], hseed, sF[s * 128 + c]);
        }
    }
    __syncthreads();

    // ---- apply: seeded scan per segment, write out (coalesced)
    {
        const int c = tid & 127;
        const int s = tid >> 7;
        float hv = sSd[s * 128 + c];
        const int mb = s * 32;
        float* op = out + (size_t)(b * Tt + t0 + mb) * Ww + hd * BW + c;
        #pragma unroll 4
        for (int mi = 0; mi < 32; ++mi) {
            int m = mb + mi;
            hv = fmaf(sA[m * 128 + c], hv, sX[m * 128 + c]);
            op[(size_t)mi * Ww] = hv;
        }
    }
}

// ---------------------------------------------------------------------------
// Cleanup: zero the flag array so the next graph replay starts from empty.
// ---------------------------------------------------------------------------
__global__ void k_reset()
{
    int i = blockIdx.x * blockDim.x + threadIdx.x;
    if (i < NSLOT) g_flag[i] = 0u;
}

// ---------------------------------------------------------------------------
extern "C" void kernel_launch(void* const* d_in, const int* in_sizes, int n_in,
                              void* d_out, int out_size)
{
    (void)in_sizes; (void)n_in; (void)out_size;
    const float* x       = (const float*)d_in[0];
    const int*   segp    = (const int*)  d_in[1];
    const float* a_param = (const float*)d_in[2];
    const float* w_in    = (const float*)d_in[3];
    const float* b_in    = (const float*)d_in[4];
    const float* w_a     = (const float*)d_in[5];
    const float* b_a     = (const float*)d_in[6];
    float* out = (float*)d_out;

    cudaFuncSetAttribute(k_fused, cudaFuncAttributeMaxDynamicSharedMemorySize,
                         SMEM_BYTES);

    k_fused<<<dim3(CC, Bb, Hh), 512, SMEM_BYTES>>>(
        x, segp, a_param, w_in, b_in, w_a, b_a, out);
    k_reset<<<(NSLOT + 511) / 512, 512>>>();
}